// round 8
// baseline (speedup 1.0000x reference)
#include <cuda_runtime.h>
#include <cuda_bf16.h>
#include <cstdint>

#define CB 4
#define CC 64
#define CH 8
#define CL 2048
#define CO 512

#define QK_SCALE 0.35355339059327373f
#define LOG2E    1.4426950408889634f

typedef unsigned long long ull;

// ---------------- bf16x2 exp2 path ----------------
__device__ __forceinline__ uint32_t cvt2bf(float hi, float lo) {
    uint32_t d; asm("cvt.rn.bf16x2.f32 %0, %1, %2;" : "=r"(d) : "f"(hi), "f"(lo)); return d;
}
__device__ __forceinline__ uint32_t ex2bf2(uint32_t x) {
    uint32_t d; asm("ex2.approx.ftz.bf16x2 %0, %1;" : "=r"(d) : "r"(x)); return d;
}
#define ONESBF 0x3F803F80u

// round-to-nearest tf32 (so tf32 mma's operand truncation is lossless)
__device__ __forceinline__ float tf32rna(float x) {
    uint32_t d; asm("cvt.rna.tf32.f32 %0, %1;" : "=r"(d) : "f"(x));
    return __uint_as_float(d);
}

// ---------------- cp.async ----------------
__device__ __forceinline__ void cpa16(uint32_t s, const void* g) {
    asm volatile("cp.async.cg.shared.global [%0], [%1], 16;" :: "r"(s), "l"(g));
}
#define CP_COMMIT() asm volatile("cp.async.commit_group;" ::: "memory")
#define CP_WAIT(n)  asm volatile("cp.async.wait_group %0;" :: "n"(n) : "memory")

__device__ __forceinline__ uint32_t smem_u32(const void* p) {
    uint32_t a;
    asm("{ .reg .u64 t; cvta.to.shared.u64 t, %1; cvt.u32.u64 %0, t; }" : "=r"(a) : "l"(p));
    return a;
}

// ---------------- HMMA m16n8k16 bf16 ----------------
__device__ __forceinline__ void hmma(float* c,
                                     uint32_t a0, uint32_t a1, uint32_t a2, uint32_t a3,
                                     uint32_t b0, uint32_t b1) {
    asm volatile(
        "mma.sync.aligned.m16n8k16.row.col.f32.bf16.bf16.f32 "
        "{%0,%1,%2,%3},{%4,%5,%6,%7},{%8,%9},{%0,%1,%2,%3};"
        : "+f"(c[0]), "+f"(c[1]), "+f"(c[2]), "+f"(c[3])
        : "r"(a0), "r"(a1), "r"(a2), "r"(a3), "r"(b0), "r"(b1));
}

// ---------------- HMMA m16n8k8 tf32 ----------------
__device__ __forceinline__ void tmma(float* c,
                                     uint32_t a0, uint32_t a1, uint32_t a2, uint32_t a3,
                                     uint32_t b0, uint32_t b1) {
    asm volatile(
        "mma.sync.aligned.m16n8k8.row.col.f32.tf32.tf32.f32 "
        "{%0,%1,%2,%3},{%4,%5,%6,%7},{%8,%9},{%0,%1,%2,%3};"
        : "+f"(c[0]), "+f"(c[1]), "+f"(c[2]), "+f"(c[3])
        : "r"(a0), "r"(a1), "r"(a2), "r"(a3), "r"(b0), "r"(b1));
}

__device__ __forceinline__ void ldsm4(uint32_t a, uint32_t& r0, uint32_t& r1,
                                      uint32_t& r2, uint32_t& r3) {
    asm volatile("ldmatrix.sync.aligned.m8n8.x4.shared.b16 {%0,%1,%2,%3}, [%4];"
        : "=r"(r0), "=r"(r1), "=r"(r2), "=r"(r3) : "r"(a));
}

// ---------------- scratch ----------------
__device__ __nv_bfloat16 g_qt[CB * CH * CL * CC];   // [bh][l][c]  (q prescaled)
__device__ __nv_bfloat16 g_kt[CB * CH * CL * CC];   // [bh][l][c]
__device__ __nv_bfloat16 g_vv[CB * CH * CC * CL];   // [bh][d][l]
__device__ float g_att[CB * CO * CL];               // tf32-rounded att
__device__ __nv_bfloat16 g_w[3 * CO * CC];          // preconverted pw (scales folded)
__device__ float g_uwt[CC * CO];                    // u_w rounded to tf32 (rna)

// ============================================================================
// Prep: pw fp32 -> bf16 (scales folded); u_w fp32 -> tf32-rna fp32.
// grid 128 x 256: first 24576 threads do pw, last 8192 do u_w (4 floats each).
// ============================================================================
__global__ __launch_bounds__(256) void prep_kernel(
    const float* __restrict__ qpw, const float* __restrict__ kpw,
    const float* __restrict__ vpw, const float* __restrict__ uw)
{
    int i = blockIdx.x * 256 + threadIdx.x;
    if (i < 24576) {
        int var = i / 8192;
        int off = (i - var * 8192) * 4;
        const float* src = (var == 0) ? qpw : (var == 1) ? kpw : vpw;
        float s = (var == 0) ? QK_SCALE * LOG2E : (var == 1) ? QK_SCALE : 1.0f;
        float4 wv = *(const float4*)&src[off];
        __nv_bfloat162 h0 = __floats2bfloat162_rn(wv.x * s, wv.y * s);
        __nv_bfloat162 h1 = __floats2bfloat162_rn(wv.z * s, wv.w * s);
        *(uint2*)&g_w[var * (CO * CC) + off] = make_uint2(*(uint32_t*)&h0, *(uint32_t*)&h1);
    } else {
        int off = (i - 24576) * 4;
        float4 wv = *(const float4*)&uw[off];
        wv.x = tf32rna(wv.x); wv.y = tf32rna(wv.y);
        wv.z = tf32rna(wv.z); wv.w = tf32rna(wv.w);
        *(float4*)&g_uwt[off] = wv;
    }
}

// ============================================================================
// QKV on HMMA. CTA = (64-seq tile, b, variant). 8 warps; warp w owns head w.
// ============================================================================
#define QKV_SMEM 82944

__global__ void __launch_bounds__(256) qkv_kernel(
    const float* __restrict__ x,
    const float* __restrict__ qdw, const float* __restrict__ qdb,
    const float* __restrict__ qpb,
    const float* __restrict__ kdw, const float* __restrict__ kdb,
    const float* __restrict__ kpb,
    const float* __restrict__ vdw, const float* __restrict__ vdb,
    const float* __restrict__ vpb)
{
    extern __shared__ char qsm[];
    __nv_bfloat16* ysb = (__nv_bfloat16*)qsm;            // [64 l][72 c]
    __nv_bfloat16* wsb = (__nv_bfloat16*)(qsm + 9216);   // [512 o][72 c]
    uint32_t sb = smem_u32(qsm);

    int var = blockIdx.z;
    const float* dw = (var == 0) ? qdw : (var == 1) ? kdw : vdw;
    const float* db = (var == 0) ? qdb : (var == 1) ? kdb : vdb;
    const float* pb = (var == 0) ? qpb : (var == 1) ? kpb : vpb;
    float bscale   = (var == 0) ? QK_SCALE * LOG2E : (var == 1) ? QK_SCALE : 1.0f;

    int l0 = blockIdx.x * 64;
    int b  = blockIdx.y;
    int tid = threadIdx.x;
    int w = tid >> 5, ln = tid & 31, gp = ln >> 2, tg = ln & 3;

    const __nv_bfloat16* wg = g_w + (size_t)var * (CO * CC);
    for (int i = tid; i < 4096; i += 256) {
        int r = i >> 3, j = i & 7;
        cpa16(sb + 9216 + r * 144 + j * 16, wg + (size_t)r * CC + j * 8);
    }
    CP_COMMIT();

    for (int idx = tid; idx < 64 * 64; idx += 256) {
        int c = idx >> 6, li = idx & 63;
        int l = l0 + li;
        const float* xr = x + (size_t)(b * CC + c) * CL;
        float w0 = dw[c * 3 + 0], w1 = dw[c * 3 + 1], w2 = dw[c * 3 + 2];
        float xm = (l > 0)      ? xr[l - 1] : 0.f;
        float x0 = xr[l];
        float xp = (l < CL - 1) ? xr[l + 1] : 0.f;
        ysb[li * 72 + c] = __float2bfloat16(db[c] + w0 * xm + w1 * x0 + w2 * xp);
    }
    CP_WAIT(0);
    __syncthreads();

    int obase = w * 64;
    float pbv[4][2];
    #pragma unroll
    for (int mt = 0; mt < 4; mt++) {
        pbv[mt][0] = pb[obase + mt * 16 + gp] * bscale;
        pbv[mt][1] = pb[obase + mt * 16 + gp + 8] * bscale;
    }

    float acc[4][8][4];
    #pragma unroll
    for (int mt = 0; mt < 4; mt++)
        #pragma unroll
        for (int n = 0; n < 8; n++)
            #pragma unroll
            for (int r = 0; r < 4; r++) acc[mt][n][r] = 0.f;

    #pragma unroll
    for (int ks = 0; ks < 4; ks++) {
        uint32_t af[4][4];
        #pragma unroll
        for (int mt = 0; mt < 4; mt++) {
            int row = obase + mt * 16 + gp;
            int col = ks * 16 + tg * 2;
            af[mt][0] = *(const uint32_t*)&wsb[(row)     * 72 + col];
            af[mt][1] = *(const uint32_t*)&wsb[(row + 8) * 72 + col];
            af[mt][2] = *(const uint32_t*)&wsb[(row)     * 72 + col + 8];
            af[mt][3] = *(const uint32_t*)&wsb[(row + 8) * 72 + col + 8];
        }
        #pragma unroll
        for (int n = 0; n < 8; n++) {
            int nrow = n * 8 + gp, ncol = ks * 16 + tg * 2;
            uint32_t b0 = *(const uint32_t*)&ysb[nrow * 72 + ncol];
            uint32_t b1 = *(const uint32_t*)&ysb[nrow * 72 + ncol + 8];
            #pragma unroll
            for (int mt = 0; mt < 4; mt++)
                hmma(acc[mt][n], af[mt][0], af[mt][1], af[mt][2], af[mt][3], b0, b1);
        }
    }

    __nv_bfloat16* stg = wsb + w * 4608;   // [64][72]
    if (var == 2) {
        #pragma unroll
        for (int mt = 0; mt < 4; mt++)
            #pragma unroll
            for (int n = 0; n < 8; n++) {
                int d = mt * 16 + gp, lcol = n * 8 + tg * 2;
                __nv_bfloat162 h0 = __floats2bfloat162_rn(acc[mt][n][0] + pbv[mt][0],
                                                          acc[mt][n][1] + pbv[mt][0]);
                __nv_bfloat162 h1 = __floats2bfloat162_rn(acc[mt][n][2] + pbv[mt][1],
                                                          acc[mt][n][3] + pbv[mt][1]);
                *(uint32_t*)&stg[(d)     * 72 + lcol] = *(uint32_t*)&h0;
                *(uint32_t*)&stg[(d + 8) * 72 + lcol] = *(uint32_t*)&h1;
            }
    } else {
        #pragma unroll
        for (int mt = 0; mt < 4; mt++)
            #pragma unroll
            for (int n = 0; n < 8; n++) {
                int d = mt * 16 + gp, lcol = n * 8 + tg * 2;
                stg[(lcol)     * 72 + d]     = __float2bfloat16(acc[mt][n][0] + pbv[mt][0]);
                stg[(lcol + 1) * 72 + d]     = __float2bfloat16(acc[mt][n][1] + pbv[mt][0]);
                stg[(lcol)     * 72 + d + 8] = __float2bfloat16(acc[mt][n][2] + pbv[mt][1]);
                stg[(lcol + 1) * 72 + d + 8] = __float2bfloat16(acc[mt][n][3] + pbv[mt][1]);
            }
    }
    __syncwarp();

    int bh = b * CH + w;
    if (var == 2) {
        for (int i = ln; i < 512; i += 32) {
            int r = i >> 3, j = i & 7;
            *(uint4*)&g_vv[((size_t)(bh * CC + r)) * CL + l0 + j * 8] =
                *(const uint4*)&stg[r * 72 + j * 8];
        }
    } else {
        __nv_bfloat16* outp = (var == 0) ? g_qt : g_kt;
        for (int i = ln; i < 512; i += 32) {
            int r = i >> 3, j = i & 7;
            *(uint4*)&outp[((size_t)bh * CL + l0 + r) * CC + j * 8] =
                *(const uint4*)&stg[r * 72 + j * 8];
        }
    }
}

// ============================================================================
// Flash attention on HMMA. Double-buffered K/V, 1 barrier/tile, occupancy 3.
// SMEM: Q [0,18432) (reused as Osm); buf j at 18432 + j*18432.
// ============================================================================
#define KT      64
#define NT      (CL / KT)
#define KV_OFF  18432
#define KV_STR  18432
#define FL_SMEM 55296

__global__ void __launch_bounds__(128, 3) flash_kernel()
{
    extern __shared__ char sm[];
    uint32_t sb = smem_u32(sm);
    __nv_bfloat16* Qsm = (__nv_bfloat16*)sm;
    float* Osm = (float*)sm;

    int tid = threadIdx.x;
    int w   = tid >> 5;
    int ln  = tid & 31;
    int gp  = ln >> 2;
    int tg  = ln & 3;
    int l0  = blockIdx.x * 128;
    int bh  = blockIdx.z * CH + blockIdx.y;

    int t4 = ln >> 3;
    uint32_t lk = (((t4 >> 1) * 8 + (ln & 7)) * 144) + ((t4 & 1) * 16);

    const __nv_bfloat16* qg = g_qt + (size_t)bh * CL * CC;
    const __nv_bfloat16* kg = g_kt + (size_t)bh * CL * CC;
    const __nv_bfloat16* vg = g_vv + (size_t)bh * CC * CL;

    // Q + tile 0 (one group)
    for (int c = tid; c < 1024; c += 128) {
        int r = c >> 3, j = c & 7;
        cpa16(sb + r * 144 + j * 16, qg + ((size_t)(l0 + r)) * CC + j * 8);
    }
    for (int c = tid; c < 512; c += 128) {
        int r = c >> 3, j = c & 7;
        cpa16(sb + KV_OFF + r * 144 + j * 16, kg + ((size_t)r) * CC + j * 8);
        cpa16(sb + KV_OFF + 9216 + r * 144 + j * 16, vg + (size_t)r * CL + j * 8);
    }
    CP_COMMIT();
    CP_WAIT(0);
    __syncthreads();

    uint32_t qa[2][4][4];
    #pragma unroll
    for (int mt = 0; mt < 2; mt++) {
        int row = w * 32 + mt * 16 + gp;
        #pragma unroll
        for (int ks = 0; ks < 4; ks++) {
            int col = ks * 16 + tg * 2;
            qa[mt][ks][0] = *(const uint32_t*)&Qsm[(row)     * 72 + col];
            qa[mt][ks][1] = *(const uint32_t*)&Qsm[(row + 8) * 72 + col];
            qa[mt][ks][2] = *(const uint32_t*)&Qsm[(row)     * 72 + col + 8];
            qa[mt][ks][3] = *(const uint32_t*)&Qsm[(row + 8) * 72 + col + 8];
        }
    }

    float Oacc[2][8][4];
    #pragma unroll
    for (int mt = 0; mt < 2; mt++)
        #pragma unroll
        for (int n = 0; n < 8; n++)
            #pragma unroll
            for (int r = 0; r < 4; r++) Oacc[mt][n][r] = 0.f;
    float Racc[2][4];
    #pragma unroll
    for (int mt = 0; mt < 2; mt++)
        #pragma unroll
        for (int r = 0; r < 4; r++) Racc[mt][r] = 0.f;

    for (int i = 0; i < NT; i++) {
        if (i > 0) CP_WAIT(0);      // tile i arrived
        __syncthreads();            // all warps done with tile i-1 (its buf = buf of i+1)

        if (i + 1 < NT) {
            int n0 = (i + 1) * KT;
            uint32_t base = sb + KV_OFF + ((i + 1) & 1) * KV_STR;
            for (int c = tid; c < 512; c += 128) {
                int r = c >> 3, j = c & 7;
                cpa16(base + r * 144 + j * 16, kg + ((size_t)(n0 + r)) * CC + j * 8);
                cpa16(base + 9216 + r * 144 + j * 16, vg + (size_t)r * CL + n0 + j * 8);
            }
            CP_COMMIT();
        }

        uint32_t kbase = sb + KV_OFF + (i & 1) * KV_STR + lk;
        uint32_t vbase = kbase + 9216;

        float Sacc[2][8][4];
        #pragma unroll
        for (int mt = 0; mt < 2; mt++)
            #pragma unroll
            for (int n = 0; n < 8; n++)
                #pragma unroll
                for (int r = 0; r < 4; r++) Sacc[mt][n][r] = 0.f;

        #pragma unroll
        for (int ks = 0; ks < 4; ks++) {
            uint32_t kb[8][2];
            #pragma unroll
            for (int ng2 = 0; ng2 < 4; ng2++)
                ldsm4(kbase + ng2 * 2304 + ks * 32,
                      kb[2 * ng2][0], kb[2 * ng2][1], kb[2 * ng2 + 1][0], kb[2 * ng2 + 1][1]);
            #pragma unroll
            for (int n = 0; n < 8; n++) {
                hmma(Sacc[0][n], qa[0][ks][0], qa[0][ks][1], qa[0][ks][2], qa[0][ks][3], kb[n][0], kb[n][1]);
                hmma(Sacc[1][n], qa[1][ks][0], qa[1][ks][1], qa[1][ks][2], qa[1][ks][3], kb[n][0], kb[n][1]);
            }
        }

        #pragma unroll
        for (int ks = 0; ks < 4; ks++) {
            uint32_t vb[8][2];
            #pragma unroll
            for (int ng2 = 0; ng2 < 4; ng2++)
                ldsm4(vbase + ng2 * 2304 + ks * 32,
                      vb[2 * ng2][0], vb[2 * ng2][1], vb[2 * ng2 + 1][0], vb[2 * ng2 + 1][1]);
            #pragma unroll
            for (int mt = 0; mt < 2; mt++) {
                uint32_t pa0 = ex2bf2(cvt2bf(Sacc[mt][2 * ks][1],     Sacc[mt][2 * ks][0]));
                uint32_t pa1 = ex2bf2(cvt2bf(Sacc[mt][2 * ks][3],     Sacc[mt][2 * ks][2]));
                uint32_t pa2 = ex2bf2(cvt2bf(Sacc[mt][2 * ks + 1][1], Sacc[mt][2 * ks + 1][0]));
                uint32_t pa3 = ex2bf2(cvt2bf(Sacc[mt][2 * ks + 1][3], Sacc[mt][2 * ks + 1][2]));
                #pragma unroll
                for (int n = 0; n < 8; n++)
                    hmma(Oacc[mt][n], pa0, pa1, pa2, pa3, vb[n][0], vb[n][1]);
                hmma(Racc[mt], pa0, pa1, pa2, pa3, ONESBF, ONESBF);
            }
        }
    }

    float inv[2][2];
    #pragma unroll
    for (int mt = 0; mt < 2; mt++) {
        inv[mt][0] = 1.0f / Racc[mt][0];
        inv[mt][1] = 1.0f / Racc[mt][2];
    }

    __syncthreads();
    #pragma unroll
    for (int mt = 0; mt < 2; mt++) {
        int qb = w * 32 + mt * 16 + gp;
        #pragma unroll
        for (int n = 0; n < 8; n++) {
            int d = n * 8 + tg * 2;
            Osm[(d)     * 132 + qb]     = Oacc[mt][n][0] * inv[mt][0];
            Osm[(d + 1) * 132 + qb]     = Oacc[mt][n][1] * inv[mt][0];
            Osm[(d)     * 132 + qb + 8] = Oacc[mt][n][2] * inv[mt][1];
            Osm[(d + 1) * 132 + qb + 8] = Oacc[mt][n][3] * inv[mt][1];
        }
    }
    __syncthreads();

    // store att pre-rounded to tf32 (rna) so unify's tf32 mma truncation is lossless
    float* ob = g_att + (size_t)bh * CC * CL + l0;
    for (int c = tid; c < 64 * 32; c += 128) {
        int d = c >> 5, q4 = (c & 31) << 2;
        float4 v = *(const float4*)&Osm[d * 132 + q4];
        v.x = tf32rna(v.x); v.y = tf32rna(v.y);
        v.z = tf32rna(v.z); v.w = tf32rna(v.w);
        *(float4*)&ob[(size_t)d * CL + q4] = v;
    }
}

// ============================================================================
// Unify heads on tf32 HMMA (operands pre-rounded rna).
// ============================================================================
#define UB_STR  34816
#define U_SMEM  (3 * UB_STR)

__global__ void __launch_bounds__(256, 1) unify_kernel(
    const float* __restrict__ ub, float* __restrict__ y)
{
    extern __shared__ float usm[];
    uint32_t sbU = smem_u32(usm);

    int tid = threadIdx.x;
    int w = tid >> 5, ln = tid & 31, gp = ln >> 2, tg = ln & 3;
    int wm = w & 3, wn = w >> 2;
    int l0 = blockIdx.x * 64, b = blockIdx.y;

    auto issue = [&](int t) {
        uint32_t base = sbU + (t % 3) * UB_STR;
        const float* ag = g_att + (size_t)(b * CO + t * 64) * CL + l0;
        for (int i = tid; i < 1024; i += 256) {
            int o = i >> 4, j = i & 15;
            cpa16(base + o * 272 + j * 16, ag + (size_t)o * CL + j * 4);
        }
        const float* wg = g_uwt + t * 64;
        for (int i = tid; i < 1024; i += 256) {
            int c = i >> 4, j = i & 15;
            cpa16(base + 17408 + c * 272 + j * 16, wg + (size_t)c * CO + j * 4);
        }
        CP_COMMIT();
    };

    issue(0);
    issue(1);

    float acc[4][4];
    #pragma unroll
    for (int ns = 0; ns < 4; ns++)
        #pragma unroll
        for (int r = 0; r < 4; r++) acc[ns][r] = 0.f;

    for (int t = 0; t < 8; t++) {
        if (t < 7) { CP_WAIT(1); } else { CP_WAIT(0); }
        __syncthreads();
        if (t + 2 < 8) issue(t + 2);

        const float* Batt = usm + (t % 3) * (UB_STR / 4);   // [o][68 l]
        const float* Aw   = Batt + 4352;                    // [c][68 o]

        #pragma unroll
        for (int ks = 0; ks < 8; ks++) {
            int k0 = ks * 8;
            int ra = (wm * 16 + gp) * 68 + k0;
            uint32_t a0 = *(const uint32_t*)&Aw[ra + tg];
            uint32_t a1 = *(const uint32_t*)&Aw[ra + 8 * 68 + tg];
            uint32_t a2 = *(const uint32_t*)&Aw[ra + tg + 4];
            uint32_t a3 = *(const uint32_t*)&Aw[ra + 8 * 68 + tg + 4];
            int rb0 = (k0 + tg) * 68 + wn * 32 + gp;
            int rb1 = (k0 + tg + 4) * 68 + wn * 32 + gp;
            #pragma unroll
            for (int ns = 0; ns < 4; ns++) {
                uint32_t b0 = *(const uint32_t*)&Batt[rb0 + ns * 8];
                uint32_t b1 = *(const uint32_t*)&Batt[rb1 + ns * 8];
                tmma(acc[ns], a0, a1, a2, a3, b0, b1);
            }
        }
    }

    __syncthreads();
    float* stg = usm;
    #pragma unroll
    for (int ns = 0; ns < 4; ns++) {
        int lcol = wn * 32 + ns * 8 + tg * 2;
        int c = wm * 16 + gp;
        *(float2*)&stg[(c)     * 68 + lcol] = make_float2(acc[ns][0], acc[ns][1]);
        *(float2*)&stg[(c + 8) * 68 + lcol] = make_float2(acc[ns][2], acc[ns][3]);
    }
    __syncthreads();

    for (int i = tid; i < 1024; i += 256) {
        int c = i >> 4, l4 = (i & 15) << 2;
        float bb = ub[c];
        float4 v = *(const float4*)&stg[c * 68 + l4];
        v.x += bb; v.y += bb; v.z += bb; v.w += bb;
        *(float4*)&y[(size_t)(b * CC + c) * CL + l0 + l4] = v;
    }
}

// ============================================================================
extern "C" void kernel_launch(void* const* d_in, const int* in_sizes, int n_in,
                              void* d_out, int out_size)
{
    (void)in_sizes; (void)n_in; (void)out_size;
    const float* x    = (const float*)d_in[0];
    const float* q_dw = (const float*)d_in[1];
    const float* q_db = (const float*)d_in[2];
    const float* q_pw = (const float*)d_in[3];
    const float* q_pb = (const float*)d_in[4];
    const float* k_dw = (const float*)d_in[5];
    const float* k_db = (const float*)d_in[6];
    const float* k_pw = (const float*)d_in[7];
    const float* k_pb = (const float*)d_in[8];
    const float* v_dw = (const float*)d_in[9];
    const float* v_db = (const float*)d_in[10];
    const float* v_pw = (const float*)d_in[11];
    const float* v_pb = (const float*)d_in[12];
    const float* u_w  = (const float*)d_in[13];
    const float* u_b  = (const float*)d_in[14];

    cudaFuncSetAttribute(qkv_kernel,
                         cudaFuncAttributeMaxDynamicSharedMemorySize, QKV_SMEM);
    cudaFuncSetAttribute(flash_kernel,
                         cudaFuncAttributeMaxDynamicSharedMemorySize, FL_SMEM);
    cudaFuncSetAttribute(unify_kernel,
                         cudaFuncAttributeMaxDynamicSharedMemorySize, U_SMEM);

    prep_kernel<<<128, 256>>>(q_pw, k_pw, v_pw, u_w);

    qkv_kernel<<<dim3(CL / 64, CB, 3), 256, QKV_SMEM>>>(
        x, q_dw, q_db, q_pb, k_dw, k_db, k_pb, v_dw, v_db, v_pb);

    flash_kernel<<<dim3(CL / 128, CH, CB), 128, FL_SMEM>>>();

    unify_kernel<<<dim3(CL / 64, CB), 256, U_SMEM>>>(u_b, (float*)d_out);
}

// round 9
// speedup vs baseline: 1.0267x; 1.0267x over previous
#include <cuda_runtime.h>
#include <cuda_bf16.h>
#include <cstdint>

#define CB 4
#define CC 64
#define CH 8
#define CL 2048
#define CO 512

#define QK_SCALE 0.35355339059327373f
#define LOG2E    1.4426950408889634f

typedef unsigned long long ull;

// ---------------- bf16x2 exp2 path ----------------
__device__ __forceinline__ uint32_t cvt2bf(float hi, float lo) {
    uint32_t d; asm("cvt.rn.bf16x2.f32 %0, %1, %2;" : "=r"(d) : "f"(hi), "f"(lo)); return d;
}
__device__ __forceinline__ uint32_t ex2bf2(uint32_t x) {
    uint32_t d; asm("ex2.approx.ftz.bf16x2 %0, %1;" : "=r"(d) : "r"(x)); return d;
}
#define ONESBF 0x3F803F80u

// round-to-nearest tf32 (so tf32 mma's operand truncation is lossless)
__device__ __forceinline__ float tf32rna(float x) {
    uint32_t d; asm("cvt.rna.tf32.f32 %0, %1;" : "=r"(d) : "f"(x));
    return __uint_as_float(d);
}

// ---------------- cp.async ----------------
__device__ __forceinline__ void cpa16(uint32_t s, const void* g) {
    asm volatile("cp.async.cg.shared.global [%0], [%1], 16;" :: "r"(s), "l"(g));
}
#define CP_COMMIT() asm volatile("cp.async.commit_group;" ::: "memory")
#define CP_WAIT(n)  asm volatile("cp.async.wait_group %0;" :: "n"(n) : "memory")

__device__ __forceinline__ uint32_t smem_u32(const void* p) {
    uint32_t a;
    asm("{ .reg .u64 t; cvta.to.shared.u64 t, %1; cvt.u32.u64 %0, t; }" : "=r"(a) : "l"(p));
    return a;
}

// ---------------- HMMA m16n8k16 bf16 ----------------
__device__ __forceinline__ void hmma(float* c,
                                     uint32_t a0, uint32_t a1, uint32_t a2, uint32_t a3,
                                     uint32_t b0, uint32_t b1) {
    asm volatile(
        "mma.sync.aligned.m16n8k16.row.col.f32.bf16.bf16.f32 "
        "{%0,%1,%2,%3},{%4,%5,%6,%7},{%8,%9},{%0,%1,%2,%3};"
        : "+f"(c[0]), "+f"(c[1]), "+f"(c[2]), "+f"(c[3])
        : "r"(a0), "r"(a1), "r"(a2), "r"(a3), "r"(b0), "r"(b1));
}

// ---------------- HMMA m16n8k8 tf32 ----------------
__device__ __forceinline__ void tmma(float* c,
                                     uint32_t a0, uint32_t a1, uint32_t a2, uint32_t a3,
                                     uint32_t b0, uint32_t b1) {
    asm volatile(
        "mma.sync.aligned.m16n8k8.row.col.f32.tf32.tf32.f32 "
        "{%0,%1,%2,%3},{%4,%5,%6,%7},{%8,%9},{%0,%1,%2,%3};"
        : "+f"(c[0]), "+f"(c[1]), "+f"(c[2]), "+f"(c[3])
        : "r"(a0), "r"(a1), "r"(a2), "r"(a3), "r"(b0), "r"(b1));
}

__device__ __forceinline__ void ldsm4(uint32_t a, uint32_t& r0, uint32_t& r1,
                                      uint32_t& r2, uint32_t& r3) {
    asm volatile("ldmatrix.sync.aligned.m8n8.x4.shared.b16 {%0,%1,%2,%3}, [%4];"
        : "=r"(r0), "=r"(r1), "=r"(r2), "=r"(r3) : "r"(a));
}

// ---------------- scratch ----------------
__device__ __nv_bfloat16 g_qt[CB * CH * CL * CC];   // [bh][l][c]  (q prescaled)
__device__ __nv_bfloat16 g_kt[CB * CH * CL * CC];   // [bh][l][c]
__device__ __nv_bfloat16 g_vv[CB * CH * CC * CL];   // [bh][d][l]
__device__ float g_att[CB * CO * CL];               // tf32-rounded att
__device__ __nv_bfloat16 g_w[3 * CO * CC];          // preconverted pw (scales folded)
__device__ float g_uwt[CC * CO];                    // u_w rounded to tf32 (rna)

// ============================================================================
// Prep
// ============================================================================
__global__ __launch_bounds__(256) void prep_kernel(
    const float* __restrict__ qpw, const float* __restrict__ kpw,
    const float* __restrict__ vpw, const float* __restrict__ uw)
{
    int i = blockIdx.x * 256 + threadIdx.x;
    if (i < 24576) {
        int var = i / 8192;
        int off = (i - var * 8192) * 4;
        const float* src = (var == 0) ? qpw : (var == 1) ? kpw : vpw;
        float s = (var == 0) ? QK_SCALE * LOG2E : (var == 1) ? QK_SCALE : 1.0f;
        float4 wv = *(const float4*)&src[off];
        __nv_bfloat162 h0 = __floats2bfloat162_rn(wv.x * s, wv.y * s);
        __nv_bfloat162 h1 = __floats2bfloat162_rn(wv.z * s, wv.w * s);
        *(uint2*)&g_w[var * (CO * CC) + off] = make_uint2(*(uint32_t*)&h0, *(uint32_t*)&h1);
    } else {
        int off = (i - 24576) * 4;
        float4 wv = *(const float4*)&uw[off];
        wv.x = tf32rna(wv.x); wv.y = tf32rna(wv.y);
        wv.z = tf32rna(wv.z); wv.w = tf32rna(wv.w);
        *(float4*)&g_uwt[off] = wv;
    }
}

// ============================================================================
// QKV on HMMA. CTA = (64-seq tile, b, variant). 512 threads, 16 warps:
// warps (2h, 2h+1) own head h; each warp computes 64 o x 32 l.
// ============================================================================
#define QKV_SMEM 82944

__global__ void __launch_bounds__(512) qkv_kernel(
    const float* __restrict__ x,
    const float* __restrict__ qdw, const float* __restrict__ qdb,
    const float* __restrict__ qpb,
    const float* __restrict__ kdw, const float* __restrict__ kdb,
    const float* __restrict__ kpb,
    const float* __restrict__ vdw, const float* __restrict__ vdb,
    const float* __restrict__ vpb)
{
    extern __shared__ char qsm[];
    __nv_bfloat16* ysb = (__nv_bfloat16*)qsm;            // [64 l][72 c]
    __nv_bfloat16* wsb = (__nv_bfloat16*)(qsm + 9216);   // [512 o][72 c]
    uint32_t sb = smem_u32(qsm);

    int var = blockIdx.z;
    const float* dw = (var == 0) ? qdw : (var == 1) ? kdw : vdw;
    const float* db = (var == 0) ? qdb : (var == 1) ? kdb : vdb;
    const float* pb = (var == 0) ? qpb : (var == 1) ? kpb : vpb;
    float bscale   = (var == 0) ? QK_SCALE * LOG2E : (var == 1) ? QK_SCALE : 1.0f;

    int l0 = blockIdx.x * 64;
    int b  = blockIdx.y;
    int tid = threadIdx.x;
    int w = tid >> 5, ln = tid & 31, gp = ln >> 2, tg = ln & 3;
    int head = w >> 1, lh = w & 1;   // warp's head, l-half (0/1 -> l cols 0-31 / 32-63)

    const __nv_bfloat16* wg = g_w + (size_t)var * (CO * CC);
    for (int i = tid; i < 4096; i += 512) {
        int r = i >> 3, j = i & 7;
        cpa16(sb + 9216 + r * 144 + j * 16, wg + (size_t)r * CC + j * 8);
    }
    CP_COMMIT();

    for (int idx = tid; idx < 64 * 64; idx += 512) {
        int c = idx >> 6, li = idx & 63;
        int l = l0 + li;
        const float* xr = x + (size_t)(b * CC + c) * CL;
        float w0 = dw[c * 3 + 0], w1 = dw[c * 3 + 1], w2 = dw[c * 3 + 2];
        float xm = (l > 0)      ? xr[l - 1] : 0.f;
        float x0 = xr[l];
        float xp = (l < CL - 1) ? xr[l + 1] : 0.f;
        ysb[li * 72 + c] = __float2bfloat16(db[c] + w0 * xm + w1 * x0 + w2 * xp);
    }
    CP_WAIT(0);
    __syncthreads();

    int obase = head * 64;
    float pbv[4][2];
    #pragma unroll
    for (int mt = 0; mt < 4; mt++) {
        pbv[mt][0] = pb[obase + mt * 16 + gp] * bscale;
        pbv[mt][1] = pb[obase + mt * 16 + gp + 8] * bscale;
    }

    float acc[4][4][4];   // [mt(o)][n(l)][frag]
    #pragma unroll
    for (int mt = 0; mt < 4; mt++)
        #pragma unroll
        for (int n = 0; n < 4; n++)
            #pragma unroll
            for (int r = 0; r < 4; r++) acc[mt][n][r] = 0.f;

    #pragma unroll
    for (int ks = 0; ks < 4; ks++) {
        uint32_t af[4][4];
        #pragma unroll
        for (int mt = 0; mt < 4; mt++) {
            int row = obase + mt * 16 + gp;
            int col = ks * 16 + tg * 2;
            af[mt][0] = *(const uint32_t*)&wsb[(row)     * 72 + col];
            af[mt][1] = *(const uint32_t*)&wsb[(row + 8) * 72 + col];
            af[mt][2] = *(const uint32_t*)&wsb[(row)     * 72 + col + 8];
            af[mt][3] = *(const uint32_t*)&wsb[(row + 8) * 72 + col + 8];
        }
        #pragma unroll
        for (int n = 0; n < 4; n++) {
            int nrow = lh * 32 + n * 8 + gp, ncol = ks * 16 + tg * 2;
            uint32_t b0 = *(const uint32_t*)&ysb[nrow * 72 + ncol];
            uint32_t b1 = *(const uint32_t*)&ysb[nrow * 72 + ncol + 8];
            #pragma unroll
            for (int mt = 0; mt < 4; mt++)
                hmma(acc[mt][n], af[mt][0], af[mt][1], af[mt][2], af[mt][3], b0, b1);
        }
    }

    __syncthreads();   // all warps done reading wsb weights before staging overwrites

    __nv_bfloat16* stg = wsb + head * 4608;   // [64][72]
    if (var == 2) {
        #pragma unroll
        for (int mt = 0; mt < 4; mt++)
            #pragma unroll
            for (int n = 0; n < 4; n++) {
                int d = mt * 16 + gp, lcol = lh * 32 + n * 8 + tg * 2;
                __nv_bfloat162 h0 = __floats2bfloat162_rn(acc[mt][n][0] + pbv[mt][0],
                                                          acc[mt][n][1] + pbv[mt][0]);
                __nv_bfloat162 h1 = __floats2bfloat162_rn(acc[mt][n][2] + pbv[mt][1],
                                                          acc[mt][n][3] + pbv[mt][1]);
                *(uint32_t*)&stg[(d)     * 72 + lcol] = *(uint32_t*)&h0;
                *(uint32_t*)&stg[(d + 8) * 72 + lcol] = *(uint32_t*)&h1;
            }
    } else {
        #pragma unroll
        for (int mt = 0; mt < 4; mt++)
            #pragma unroll
            for (int n = 0; n < 4; n++) {
                int d = mt * 16 + gp, lcol = lh * 32 + n * 8 + tg * 2;
                stg[(lcol)     * 72 + d]     = __float2bfloat16(acc[mt][n][0] + pbv[mt][0]);
                stg[(lcol + 1) * 72 + d]     = __float2bfloat16(acc[mt][n][1] + pbv[mt][0]);
                stg[(lcol)     * 72 + d + 8] = __float2bfloat16(acc[mt][n][2] + pbv[mt][1]);
                stg[(lcol + 1) * 72 + d + 8] = __float2bfloat16(acc[mt][n][3] + pbv[mt][1]);
            }
    }
    __syncthreads();

    int bh = b * CH + head;
    int lane64 = lh * 32 + ln;   // 64 lanes per head region
    if (var == 2) {
        for (int i = lane64; i < 512; i += 64) {
            int r = i >> 3, j = i & 7;
            *(uint4*)&g_vv[((size_t)(bh * CC + r)) * CL + l0 + j * 8] =
                *(const uint4*)&stg[r * 72 + j * 8];
        }
    } else {
        __nv_bfloat16* outp = (var == 0) ? g_qt : g_kt;
        for (int i = lane64; i < 512; i += 64) {
            int r = i >> 3, j = i & 7;
            *(uint4*)&outp[((size_t)bh * CL + l0 + r) * CC + j * 8] =
                *(const uint4*)&stg[r * 72 + j * 8];
        }
    }
}

// ============================================================================
// Flash attention on HMMA. Double-buffered K/V, 1 barrier/tile, occupancy 3.
// Q fragments re-ldmatrix'd from smem each tile (saves 32 regs -> real occ 3).
// ============================================================================
#define KT      64
#define NT      (CL / KT)
#define KV_OFF  18432
#define KV_STR  18432
#define FL_SMEM 55296

__global__ void __launch_bounds__(128, 3) flash_kernel()
{
    extern __shared__ char sm[];
    uint32_t sb = smem_u32(sm);
    float* Osm = (float*)sm;

    int tid = threadIdx.x;
    int w   = tid >> 5;
    int ln  = tid & 31;
    int gp  = ln >> 2;
    int tg  = ln & 3;
    int l0  = blockIdx.x * 128;
    int bh  = blockIdx.z * CH + blockIdx.y;

    int t4 = ln >> 3;
    // B-fragment ldmatrix lane offset (row-within-2-n-group block, bytes)
    uint32_t lk = (((t4 >> 1) * 8 + (ln & 7)) * 144) + ((t4 & 1) * 16);
    // A-fragment ldmatrix lane offset: lanes 8-15 -> rows+8, lanes 16-31 -> cols+8
    uint32_t qlk = (((t4 & 1) * 8 + (ln & 7)) * 144) + ((t4 >> 1) * 16);
    uint32_t qwarp = sb + (uint32_t)(w * 32) * 144 + qlk;

    const __nv_bfloat16* qg = g_qt + (size_t)bh * CL * CC;
    const __nv_bfloat16* kg = g_kt + (size_t)bh * CL * CC;
    const __nv_bfloat16* vg = g_vv + (size_t)bh * CC * CL;

    for (int c = tid; c < 1024; c += 128) {
        int r = c >> 3, j = c & 7;
        cpa16(sb + r * 144 + j * 16, qg + ((size_t)(l0 + r)) * CC + j * 8);
    }
    for (int c = tid; c < 512; c += 128) {
        int r = c >> 3, j = c & 7;
        cpa16(sb + KV_OFF + r * 144 + j * 16, kg + ((size_t)r) * CC + j * 8);
        cpa16(sb + KV_OFF + 9216 + r * 144 + j * 16, vg + (size_t)r * CL + j * 8);
    }
    CP_COMMIT();
    CP_WAIT(0);
    __syncthreads();

    float Oacc[2][8][4];
    #pragma unroll
    for (int mt = 0; mt < 2; mt++)
        #pragma unroll
        for (int n = 0; n < 8; n++)
            #pragma unroll
            for (int r = 0; r < 4; r++) Oacc[mt][n][r] = 0.f;
    float Racc[2][4];
    #pragma unroll
    for (int mt = 0; mt < 2; mt++)
        #pragma unroll
        for (int r = 0; r < 4; r++) Racc[mt][r] = 0.f;

    for (int i = 0; i < NT; i++) {
        if (i > 0) CP_WAIT(0);
        __syncthreads();

        if (i + 1 < NT) {
            int n0 = (i + 1) * KT;
            uint32_t base = sb + KV_OFF + ((i + 1) & 1) * KV_STR;
            for (int c = tid; c < 512; c += 128) {
                int r = c >> 3, j = c & 7;
                cpa16(base + r * 144 + j * 16, kg + ((size_t)(n0 + r)) * CC + j * 8);
                cpa16(base + 9216 + r * 144 + j * 16, vg + (size_t)r * CL + n0 + j * 8);
            }
            CP_COMMIT();
        }

        uint32_t kbase = sb + KV_OFF + (i & 1) * KV_STR + lk;
        uint32_t vbase = kbase + 9216;

        float Sacc[2][8][4];
        #pragma unroll
        for (int mt = 0; mt < 2; mt++)
            #pragma unroll
            for (int n = 0; n < 8; n++)
                #pragma unroll
                for (int r = 0; r < 4; r++) Sacc[mt][n][r] = 0.f;

        // ---- MMA1: S = Q . K^T (Q frags streamed via ldmatrix) ----
        #pragma unroll
        for (int ks = 0; ks < 4; ks++) {
            uint32_t qf[2][4];
            #pragma unroll
            for (int mt = 0; mt < 2; mt++)
                ldsm4(qwarp + (uint32_t)(mt * 16) * 144 + ks * 32,
                      qf[mt][0], qf[mt][1], qf[mt][2], qf[mt][3]);
            #pragma unroll
            for (int ng2 = 0; ng2 < 4; ng2++) {
                uint32_t k0, k1, k2, k3;
                ldsm4(kbase + ng2 * 2304 + ks * 32, k0, k1, k2, k3);
                hmma(Sacc[0][2 * ng2],     qf[0][0], qf[0][1], qf[0][2], qf[0][3], k0, k1);
                hmma(Sacc[0][2 * ng2 + 1], qf[0][0], qf[0][1], qf[0][2], qf[0][3], k2, k3);
                hmma(Sacc[1][2 * ng2],     qf[1][0], qf[1][1], qf[1][2], qf[1][3], k0, k1);
                hmma(Sacc[1][2 * ng2 + 1], qf[1][0], qf[1][1], qf[1][2], qf[1][3], k2, k3);
            }
        }

        // ---- P = ex2(S); O += P.V; rowsum += P.ones ----
        #pragma unroll
        for (int ks = 0; ks < 4; ks++) {
            uint32_t pa[2][4];
            #pragma unroll
            for (int mt = 0; mt < 2; mt++) {
                pa[mt][0] = ex2bf2(cvt2bf(Sacc[mt][2 * ks][1],     Sacc[mt][2 * ks][0]));
                pa[mt][1] = ex2bf2(cvt2bf(Sacc[mt][2 * ks][3],     Sacc[mt][2 * ks][2]));
                pa[mt][2] = ex2bf2(cvt2bf(Sacc[mt][2 * ks + 1][1], Sacc[mt][2 * ks + 1][0]));
                pa[mt][3] = ex2bf2(cvt2bf(Sacc[mt][2 * ks + 1][3], Sacc[mt][2 * ks + 1][2]));
            }
            #pragma unroll
            for (int ng2 = 0; ng2 < 4; ng2++) {
                uint32_t v0, v1, v2, v3;
                ldsm4(vbase + ng2 * 2304 + ks * 32, v0, v1, v2, v3);
                hmma(Oacc[0][2 * ng2],     pa[0][0], pa[0][1], pa[0][2], pa[0][3], v0, v1);
                hmma(Oacc[0][2 * ng2 + 1], pa[0][0], pa[0][1], pa[0][2], pa[0][3], v2, v3);
                hmma(Oacc[1][2 * ng2],     pa[1][0], pa[1][1], pa[1][2], pa[1][3], v0, v1);
                hmma(Oacc[1][2 * ng2 + 1], pa[1][0], pa[1][1], pa[1][2], pa[1][3], v2, v3);
            }
            hmma(Racc[0], pa[0][0], pa[0][1], pa[0][2], pa[0][3], ONESBF, ONESBF);
            hmma(Racc[1], pa[1][0], pa[1][1], pa[1][2], pa[1][3], ONESBF, ONESBF);
        }
    }

    float inv[2][2];
    #pragma unroll
    for (int mt = 0; mt < 2; mt++) {
        inv[mt][0] = 1.0f / Racc[mt][0];
        inv[mt][1] = 1.0f / Racc[mt][2];
    }

    __syncthreads();
    #pragma unroll
    for (int mt = 0; mt < 2; mt++) {
        int qb = w * 32 + mt * 16 + gp;
        #pragma unroll
        for (int n = 0; n < 8; n++) {
            int d = n * 8 + tg * 2;
            Osm[(d)     * 132 + qb]     = Oacc[mt][n][0] * inv[mt][0];
            Osm[(d + 1) * 132 + qb]     = Oacc[mt][n][1] * inv[mt][0];
            Osm[(d)     * 132 + qb + 8] = Oacc[mt][n][2] * inv[mt][1];
            Osm[(d + 1) * 132 + qb + 8] = Oacc[mt][n][3] * inv[mt][1];
        }
    }
    __syncthreads();

    float* ob = g_att + (size_t)bh * CC * CL + l0;
    for (int c = tid; c < 64 * 32; c += 128) {
        int d = c >> 5, q4 = (c & 31) << 2;
        float4 v = *(const float4*)&Osm[d * 132 + q4];
        v.x = tf32rna(v.x); v.y = tf32rna(v.y);
        v.z = tf32rna(v.z); v.w = tf32rna(v.w);
        *(float4*)&ob[(size_t)d * CL + q4] = v;
    }
}

// ============================================================================
// Unify heads on tf32 HMMA (operands pre-rounded rna).
// ============================================================================
#define UB_STR  34816
#define U_SMEM  (3 * UB_STR)

__global__ void __launch_bounds__(256, 1) unify_kernel(
    const float* __restrict__ ub, float* __restrict__ y)
{
    extern __shared__ float usm[];
    uint32_t sbU = smem_u32(usm);

    int tid = threadIdx.x;
    int w = tid >> 5, ln = tid & 31, gp = ln >> 2, tg = ln & 3;
    int wm = w & 3, wn = w >> 2;
    int l0 = blockIdx.x * 64, b = blockIdx.y;

    auto issue = [&](int t) {
        uint32_t base = sbU + (t % 3) * UB_STR;
        const float* ag = g_att + (size_t)(b * CO + t * 64) * CL + l0;
        for (int i = tid; i < 1024; i += 256) {
            int o = i >> 4, j = i & 15;
            cpa16(base + o * 272 + j * 16, ag + (size_t)o * CL + j * 4);
        }
        const float* wg = g_uwt + t * 64;
        for (int i = tid; i < 1024; i += 256) {
            int c = i >> 4, j = i & 15;
            cpa16(base + 17408 + c * 272 + j * 16, wg + (size_t)c * CO + j * 4);
        }
        CP_COMMIT();
    };

    issue(0);
    issue(1);

    float acc[4][4];
    #pragma unroll
    for (int ns = 0; ns < 4; ns++)
        #pragma unroll
        for (int r = 0; r < 4; r++) acc[ns][r] = 0.f;

    for (int t = 0; t < 8; t++) {
        if (t < 7) { CP_WAIT(1); } else { CP_WAIT(0); }
        __syncthreads();
        if (t + 2 < 8) issue(t + 2);

        const float* Batt = usm + (t % 3) * (UB_STR / 4);   // [o][68 l]
        const float* Aw   = Batt + 4352;                    // [c][68 o]

        #pragma unroll
        for (int ks = 0; ks < 8; ks++) {
            int k0 = ks * 8;
            int ra = (wm * 16 + gp) * 68 + k0;
            uint32_t a0 = *(const uint32_t*)&Aw[ra + tg];
            uint32_t a1 = *(const uint32_t*)&Aw[ra + 8 * 68 + tg];
            uint32_t a2 = *(const uint32_t*)&Aw[ra + tg + 4];
            uint32_t a3 = *(const uint32_t*)&Aw[ra + 8 * 68 + tg + 4];
            int rb0 = (k0 + tg) * 68 + wn * 32 + gp;
            int rb1 = (k0 + tg + 4) * 68 + wn * 32 + gp;
            #pragma unroll
            for (int ns = 0; ns < 4; ns++) {
                uint32_t b0 = *(const uint32_t*)&Batt[rb0 + ns * 8];
                uint32_t b1 = *(const uint32_t*)&Batt[rb1 + ns * 8];
                tmma(acc[ns], a0, a1, a2, a3, b0, b1);
            }
        }
    }

    __syncthreads();
    float* stg = usm;
    #pragma unroll
    for (int ns = 0; ns < 4; ns++) {
        int lcol = wn * 32 + ns * 8 + tg * 2;
        int c = wm * 16 + gp;
        *(float2*)&stg[(c)     * 68 + lcol] = make_float2(acc[ns][0], acc[ns][1]);
        *(float2*)&stg[(c + 8) * 68 + lcol] = make_float2(acc[ns][2], acc[ns][3]);
    }
    __syncthreads();

    for (int i = tid; i < 1024; i += 256) {
        int c = i >> 4, l4 = (i & 15) << 2;
        float bb = ub[c];
        float4 v = *(const float4*)&stg[c * 68 + l4];
        v.x += bb; v.y += bb; v.z += bb; v.w += bb;
        *(float4*)&y[(size_t)(b * CC + c) * CL + l0 + l4] = v;
    }
}

// ============================================================================
extern "C" void kernel_launch(void* const* d_in, const int* in_sizes, int n_in,
                              void* d_out, int out_size)
{
    (void)in_sizes; (void)n_in; (void)out_size;
    const float* x    = (const float*)d_in[0];
    const float* q_dw = (const float*)d_in[1];
    const float* q_db = (const float*)d_in[2];
    const float* q_pw = (const float*)d_in[3];
    const float* q_pb = (const float*)d_in[4];
    const float* k_dw = (const float*)d_in[5];
    const float* k_db = (const float*)d_in[6];
    const float* k_pw = (const float*)d_in[7];
    const float* k_pb = (const float*)d_in[8];
    const float* v_dw = (const float*)d_in[9];
    const float* v_db = (const float*)d_in[10];
    const float* v_pw = (const float*)d_in[11];
    const float* v_pb = (const float*)d_in[12];
    const float* u_w  = (const float*)d_in[13];
    const float* u_b  = (const float*)d_in[14];

    cudaFuncSetAttribute(qkv_kernel,
                         cudaFuncAttributeMaxDynamicSharedMemorySize, QKV_SMEM);
    cudaFuncSetAttribute(flash_kernel,
                         cudaFuncAttributeMaxDynamicSharedMemorySize, FL_SMEM);
    cudaFuncSetAttribute(unify_kernel,
                         cudaFuncAttributeMaxDynamicSharedMemorySize, U_SMEM);

    prep_kernel<<<128, 256>>>(q_pw, k_pw, v_pw, u_w);

    qkv_kernel<<<dim3(CL / 64, CB, 3), 512, QKV_SMEM>>>(
        x, q_dw, q_db, q_pb, k_dw, k_db, k_pb, v_dw, v_db, v_pb);

    flash_kernel<<<dim3(CL / 128, CH, CB), 128, FL_SMEM>>>();

    unify_kernel<<<dim3(CL / 64, CB), 256, U_SMEM>>>(u_b, (float*)d_out);
}

// round 10
// speedup vs baseline: 1.0656x; 1.0379x over previous
#include <cuda_runtime.h>
#include <cuda_bf16.h>
#include <cstdint>

#define CB 4
#define CC 64
#define CH 8
#define CL 2048
#define CO 512

#define QK_SCALE 0.35355339059327373f
#define LOG2E    1.4426950408889634f

typedef unsigned long long ull;

// ---------------- bf16x2 exp2 path ----------------
__device__ __forceinline__ uint32_t cvt2bf(float hi, float lo) {
    uint32_t d; asm("cvt.rn.bf16x2.f32 %0, %1, %2;" : "=r"(d) : "f"(hi), "f"(lo)); return d;
}
__device__ __forceinline__ uint32_t ex2bf2(uint32_t x) {
    uint32_t d; asm("ex2.approx.ftz.bf16x2 %0, %1;" : "=r"(d) : "r"(x)); return d;
}
#define ONESBF 0x3F803F80u

// round-to-nearest tf32 (so tf32 mma's operand truncation is lossless)
__device__ __forceinline__ float tf32rna(float x) {
    uint32_t d; asm("cvt.rna.tf32.f32 %0, %1;" : "=r"(d) : "f"(x));
    return __uint_as_float(d);
}

// ---------------- cp.async ----------------
__device__ __forceinline__ void cpa16(uint32_t s, const void* g) {
    asm volatile("cp.async.cg.shared.global [%0], [%1], 16;" :: "r"(s), "l"(g));
}
#define CP_COMMIT() asm volatile("cp.async.commit_group;" ::: "memory")
#define CP_WAIT(n)  asm volatile("cp.async.wait_group %0;" :: "n"(n) : "memory")

__device__ __forceinline__ uint32_t smem_u32(const void* p) {
    uint32_t a;
    asm("{ .reg .u64 t; cvta.to.shared.u64 t, %1; cvt.u32.u64 %0, t; }" : "=r"(a) : "l"(p));
    return a;
}

// ---------------- HMMA m16n8k16 bf16 ----------------
__device__ __forceinline__ void hmma(float* c,
                                     uint32_t a0, uint32_t a1, uint32_t a2, uint32_t a3,
                                     uint32_t b0, uint32_t b1) {
    asm volatile(
        "mma.sync.aligned.m16n8k16.row.col.f32.bf16.bf16.f32 "
        "{%0,%1,%2,%3},{%4,%5,%6,%7},{%8,%9},{%0,%1,%2,%3};"
        : "+f"(c[0]), "+f"(c[1]), "+f"(c[2]), "+f"(c[3])
        : "r"(a0), "r"(a1), "r"(a2), "r"(a3), "r"(b0), "r"(b1));
}

// HMMA with C = constant zeros (D written, no explicit accumulator zeroing)
__device__ __forceinline__ void hmma_z(float* d,
                                       uint32_t a0, uint32_t a1, uint32_t a2, uint32_t a3,
                                       uint32_t b0, uint32_t b1) {
    asm volatile(
        "mma.sync.aligned.m16n8k16.row.col.f32.bf16.bf16.f32 "
        "{%0,%1,%2,%3},{%4,%5,%6,%7},{%8,%9},{%10,%11,%12,%13};"
        : "=f"(d[0]), "=f"(d[1]), "=f"(d[2]), "=f"(d[3])
        : "r"(a0), "r"(a1), "r"(a2), "r"(a3), "r"(b0), "r"(b1),
          "f"(0.f), "f"(0.f), "f"(0.f), "f"(0.f));
}

// ---------------- HMMA m16n8k8 tf32 ----------------
__device__ __forceinline__ void tmma(float* c,
                                     uint32_t a0, uint32_t a1, uint32_t a2, uint32_t a3,
                                     uint32_t b0, uint32_t b1) {
    asm volatile(
        "mma.sync.aligned.m16n8k8.row.col.f32.tf32.tf32.f32 "
        "{%0,%1,%2,%3},{%4,%5,%6,%7},{%8,%9},{%0,%1,%2,%3};"
        : "+f"(c[0]), "+f"(c[1]), "+f"(c[2]), "+f"(c[3])
        : "r"(a0), "r"(a1), "r"(a2), "r"(a3), "r"(b0), "r"(b1));
}

__device__ __forceinline__ void ldsm4(uint32_t a, uint32_t& r0, uint32_t& r1,
                                      uint32_t& r2, uint32_t& r3) {
    asm volatile("ldmatrix.sync.aligned.m8n8.x4.shared.b16 {%0,%1,%2,%3}, [%4];"
        : "=r"(r0), "=r"(r1), "=r"(r2), "=r"(r3) : "r"(a));
}

// ---------------- scratch ----------------
__device__ __nv_bfloat16 g_qt[CB * CH * CL * CC];   // [bh][l][c]  (q prescaled)
__device__ __nv_bfloat16 g_kt[CB * CH * CL * CC];   // [bh][l][c]
__device__ __nv_bfloat16 g_vv[CB * CH * CC * CL];   // [bh][d][l]
__device__ float g_att[2 * CB * CO * CL];           // raw partial O, per split
__device__ float g_rs[2 * CB * CH * CL];            // partial rowsums, per split
__device__ __nv_bfloat16 g_w[3 * CO * CC];          // preconverted pw (scales folded)
__device__ float g_uwt[CC * CO];                    // u_w rounded to tf32 (rna)

// ============================================================================
// Prep
// ============================================================================
__global__ __launch_bounds__(256) void prep_kernel(
    const float* __restrict__ qpw, const float* __restrict__ kpw,
    const float* __restrict__ vpw, const float* __restrict__ uw)
{
    int i = blockIdx.x * 256 + threadIdx.x;
    if (i < 24576) {
        int var = i / 8192;
        int off = (i - var * 8192) * 4;
        const float* src = (var == 0) ? qpw : (var == 1) ? kpw : vpw;
        float s = (var == 0) ? QK_SCALE * LOG2E : (var == 1) ? QK_SCALE : 1.0f;
        float4 wv = *(const float4*)&src[off];
        __nv_bfloat162 h0 = __floats2bfloat162_rn(wv.x * s, wv.y * s);
        __nv_bfloat162 h1 = __floats2bfloat162_rn(wv.z * s, wv.w * s);
        *(uint2*)&g_w[var * (CO * CC) + off] = make_uint2(*(uint32_t*)&h0, *(uint32_t*)&h1);
    } else {
        int off = (i - 24576) * 4;
        float4 wv = *(const float4*)&uw[off];
        wv.x = tf32rna(wv.x); wv.y = tf32rna(wv.y);
        wv.z = tf32rna(wv.z); wv.w = tf32rna(wv.w);
        *(float4*)&g_uwt[off] = wv;
    }
}

// ============================================================================
// QKV on HMMA. CTA = (64-seq tile, b, variant). 512 threads, 16 warps.
// ============================================================================
#define QKV_SMEM 82944

__global__ void __launch_bounds__(512) qkv_kernel(
    const float* __restrict__ x,
    const float* __restrict__ qdw, const float* __restrict__ qdb,
    const float* __restrict__ qpb,
    const float* __restrict__ kdw, const float* __restrict__ kdb,
    const float* __restrict__ kpb,
    const float* __restrict__ vdw, const float* __restrict__ vdb,
    const float* __restrict__ vpb)
{
    extern __shared__ char qsm[];
    __nv_bfloat16* ysb = (__nv_bfloat16*)qsm;            // [64 l][72 c]
    __nv_bfloat16* wsb = (__nv_bfloat16*)(qsm + 9216);   // [512 o][72 c]
    uint32_t sb = smem_u32(qsm);

    int var = blockIdx.z;
    const float* dw = (var == 0) ? qdw : (var == 1) ? kdw : vdw;
    const float* db = (var == 0) ? qdb : (var == 1) ? kdb : vdb;
    const float* pb = (var == 0) ? qpb : (var == 1) ? kpb : vpb;
    float bscale   = (var == 0) ? QK_SCALE * LOG2E : (var == 1) ? QK_SCALE : 1.0f;

    int l0 = blockIdx.x * 64;
    int b  = blockIdx.y;
    int tid = threadIdx.x;
    int w = tid >> 5, ln = tid & 31, gp = ln >> 2, tg = ln & 3;
    int head = w >> 1, lh = w & 1;

    const __nv_bfloat16* wg = g_w + (size_t)var * (CO * CC);
    for (int i = tid; i < 4096; i += 512) {
        int r = i >> 3, j = i & 7;
        cpa16(sb + 9216 + r * 144 + j * 16, wg + (size_t)r * CC + j * 8);
    }
    CP_COMMIT();

    for (int idx = tid; idx < 64 * 64; idx += 512) {
        int c = idx >> 6, li = idx & 63;
        int l = l0 + li;
        const float* xr = x + (size_t)(b * CC + c) * CL;
        float w0 = dw[c * 3 + 0], w1 = dw[c * 3 + 1], w2 = dw[c * 3 + 2];
        float xm = (l > 0)      ? xr[l - 1] : 0.f;
        float x0 = xr[l];
        float xp = (l < CL - 1) ? xr[l + 1] : 0.f;
        ysb[li * 72 + c] = __float2bfloat16(db[c] + w0 * xm + w1 * x0 + w2 * xp);
    }
    CP_WAIT(0);
    __syncthreads();

    int obase = head * 64;
    float pbv[4][2];
    #pragma unroll
    for (int mt = 0; mt < 4; mt++) {
        pbv[mt][0] = pb[obase + mt * 16 + gp] * bscale;
        pbv[mt][1] = pb[obase + mt * 16 + gp + 8] * bscale;
    }

    float acc[4][4][4];
    #pragma unroll
    for (int mt = 0; mt < 4; mt++)
        #pragma unroll
        for (int n = 0; n < 4; n++)
            #pragma unroll
            for (int r = 0; r < 4; r++) acc[mt][n][r] = 0.f;

    #pragma unroll
    for (int ks = 0; ks < 4; ks++) {
        uint32_t af[4][4];
        #pragma unroll
        for (int mt = 0; mt < 4; mt++) {
            int row = obase + mt * 16 + gp;
            int col = ks * 16 + tg * 2;
            af[mt][0] = *(const uint32_t*)&wsb[(row)     * 72 + col];
            af[mt][1] = *(const uint32_t*)&wsb[(row + 8) * 72 + col];
            af[mt][2] = *(const uint32_t*)&wsb[(row)     * 72 + col + 8];
            af[mt][3] = *(const uint32_t*)&wsb[(row + 8) * 72 + col + 8];
        }
        #pragma unroll
        for (int n = 0; n < 4; n++) {
            int nrow = lh * 32 + n * 8 + gp, ncol = ks * 16 + tg * 2;
            uint32_t b0 = *(const uint32_t*)&ysb[nrow * 72 + ncol];
            uint32_t b1 = *(const uint32_t*)&ysb[nrow * 72 + ncol + 8];
            #pragma unroll
            for (int mt = 0; mt < 4; mt++)
                hmma(acc[mt][n], af[mt][0], af[mt][1], af[mt][2], af[mt][3], b0, b1);
        }
    }

    __syncthreads();

    __nv_bfloat16* stg = wsb + head * 4608;   // [64][72]
    if (var == 2) {
        #pragma unroll
        for (int mt = 0; mt < 4; mt++)
            #pragma unroll
            for (int n = 0; n < 4; n++) {
                int d = mt * 16 + gp, lcol = lh * 32 + n * 8 + tg * 2;
                __nv_bfloat162 h0 = __floats2bfloat162_rn(acc[mt][n][0] + pbv[mt][0],
                                                          acc[mt][n][1] + pbv[mt][0]);
                __nv_bfloat162 h1 = __floats2bfloat162_rn(acc[mt][n][2] + pbv[mt][1],
                                                          acc[mt][n][3] + pbv[mt][1]);
                *(uint32_t*)&stg[(d)     * 72 + lcol] = *(uint32_t*)&h0;
                *(uint32_t*)&stg[(d + 8) * 72 + lcol] = *(uint32_t*)&h1;
            }
    } else {
        #pragma unroll
        for (int mt = 0; mt < 4; mt++)
            #pragma unroll
            for (int n = 0; n < 4; n++) {
                int d = mt * 16 + gp, lcol = lh * 32 + n * 8 + tg * 2;
                stg[(lcol)     * 72 + d]     = __float2bfloat16(acc[mt][n][0] + pbv[mt][0]);
                stg[(lcol + 1) * 72 + d]     = __float2bfloat16(acc[mt][n][1] + pbv[mt][0]);
                stg[(lcol)     * 72 + d + 8] = __float2bfloat16(acc[mt][n][2] + pbv[mt][1]);
                stg[(lcol + 1) * 72 + d + 8] = __float2bfloat16(acc[mt][n][3] + pbv[mt][1]);
            }
    }
    __syncthreads();

    int bh = b * CH + head;
    int lane64 = lh * 32 + ln;
    if (var == 2) {
        for (int i = lane64; i < 512; i += 64) {
            int r = i >> 3, j = i & 7;
            *(uint4*)&g_vv[((size_t)(bh * CC + r)) * CL + l0 + j * 8] =
                *(const uint4*)&stg[r * 72 + j * 8];
        }
    } else {
        __nv_bfloat16* outp = (var == 0) ? g_qt : g_kt;
        for (int i = lane64; i < 512; i += 64) {
            int r = i >> 3, j = i & 7;
            *(uint4*)&outp[((size_t)bh * CL + l0 + r) * CC + j * 8] =
                *(const uint4*)&stg[r * 72 + j * 8];
        }
    }
}

// ============================================================================
// Flash attention, split-K=2: CTA = (q-tile, h, b*2+s); keys [s*1024,(s+1)*1024).
// Stores raw partial O (fp32) + partial rowsums; unify combines + normalizes.
// ============================================================================
#define KT      64
#define NT      (CL / KT / 2)   // 16 tiles per split
#define KV_OFF  18432
#define KV_STR  18432
#define FL_SMEM 55296

__global__ void __launch_bounds__(128, 3) flash_kernel()
{
    extern __shared__ char sm[];
    uint32_t sb = smem_u32(sm);
    float* Osm = (float*)sm;

    int tid = threadIdx.x;
    int w   = tid >> 5;
    int ln  = tid & 31;
    int gp  = ln >> 2;
    int tg  = ln & 3;
    int l0  = blockIdx.x * 128;
    int s   = blockIdx.z & 1;
    int bh  = (blockIdx.z >> 1) * CH + blockIdx.y;
    int kbase0 = s * (CL / 2);

    int t4 = ln >> 3;
    uint32_t lk  = (((t4 >> 1) * 8 + (ln & 7)) * 144) + ((t4 & 1) * 16);
    uint32_t qlk = (((t4 & 1) * 8 + (ln & 7)) * 144) + ((t4 >> 1) * 16);
    uint32_t qwarp = sb + (uint32_t)(w * 32) * 144 + qlk;

    const __nv_bfloat16* qg = g_qt + (size_t)bh * CL * CC;
    const __nv_bfloat16* kg = g_kt + (size_t)bh * CL * CC;
    const __nv_bfloat16* vg = g_vv + (size_t)bh * CC * CL;

    for (int c = tid; c < 1024; c += 128) {
        int r = c >> 3, j = c & 7;
        cpa16(sb + r * 144 + j * 16, qg + ((size_t)(l0 + r)) * CC + j * 8);
    }
    for (int c = tid; c < 512; c += 128) {
        int r = c >> 3, j = c & 7;
        cpa16(sb + KV_OFF + r * 144 + j * 16, kg + ((size_t)(kbase0 + r)) * CC + j * 8);
        cpa16(sb + KV_OFF + 9216 + r * 144 + j * 16, vg + (size_t)r * CL + kbase0 + j * 8);
    }
    CP_COMMIT();
    CP_WAIT(0);
    __syncthreads();

    float Oacc[2][8][4];
    #pragma unroll
    for (int mt = 0; mt < 2; mt++)
        #pragma unroll
        for (int n = 0; n < 8; n++)
            #pragma unroll
            for (int r = 0; r < 4; r++) Oacc[mt][n][r] = 0.f;
    float Racc[2][4];
    #pragma unroll
    for (int mt = 0; mt < 2; mt++)
        #pragma unroll
        for (int r = 0; r < 4; r++) Racc[mt][r] = 0.f;

    for (int i = 0; i < NT; i++) {
        if (i > 0) CP_WAIT(0);
        __syncthreads();

        if (i + 1 < NT) {
            int n0 = kbase0 + (i + 1) * KT;
            uint32_t base = sb + KV_OFF + ((i + 1) & 1) * KV_STR;
            for (int c = tid; c < 512; c += 128) {
                int r = c >> 3, j = c & 7;
                cpa16(base + r * 144 + j * 16, kg + ((size_t)(n0 + r)) * CC + j * 8);
                cpa16(base + 9216 + r * 144 + j * 16, vg + (size_t)r * CL + n0 + j * 8);
            }
            CP_COMMIT();
        }

        uint32_t kb = sb + KV_OFF + (i & 1) * KV_STR + lk;
        uint32_t vb = kb + 9216;

        float Sacc[2][8][4];

        // ---- MMA1: S = Q . K^T (ks=0 writes Sacc via zero-C; no explicit zeroing) ----
        #pragma unroll
        for (int ks = 0; ks < 4; ks++) {
            uint32_t qf[2][4];
            #pragma unroll
            for (int mt = 0; mt < 2; mt++)
                ldsm4(qwarp + (uint32_t)(mt * 16) * 144 + ks * 32,
                      qf[mt][0], qf[mt][1], qf[mt][2], qf[mt][3]);
            #pragma unroll
            for (int ng2 = 0; ng2 < 4; ng2++) {
                uint32_t k0, k1, k2, k3;
                ldsm4(kb + ng2 * 2304 + ks * 32, k0, k1, k2, k3);
                if (ks == 0) {
                    hmma_z(Sacc[0][2 * ng2],     qf[0][0], qf[0][1], qf[0][2], qf[0][3], k0, k1);
                    hmma_z(Sacc[0][2 * ng2 + 1], qf[0][0], qf[0][1], qf[0][2], qf[0][3], k2, k3);
                    hmma_z(Sacc[1][2 * ng2],     qf[1][0], qf[1][1], qf[1][2], qf[1][3], k0, k1);
                    hmma_z(Sacc[1][2 * ng2 + 1], qf[1][0], qf[1][1], qf[1][2], qf[1][3], k2, k3);
                } else {
                    hmma(Sacc[0][2 * ng2],     qf[0][0], qf[0][1], qf[0][2], qf[0][3], k0, k1);
                    hmma(Sacc[0][2 * ng2 + 1], qf[0][0], qf[0][1], qf[0][2], qf[0][3], k2, k3);
                    hmma(Sacc[1][2 * ng2],     qf[1][0], qf[1][1], qf[1][2], qf[1][3], k0, k1);
                    hmma(Sacc[1][2 * ng2 + 1], qf[1][0], qf[1][1], qf[1][2], qf[1][3], k2, k3);
                }
            }
        }

        // ---- P = ex2(S); O += P.V; rowsum += P.ones ----
        #pragma unroll
        for (int ks = 0; ks < 4; ks++) {
            uint32_t pa[2][4];
            #pragma unroll
            for (int mt = 0; mt < 2; mt++) {
                pa[mt][0] = ex2bf2(cvt2bf(Sacc[mt][2 * ks][1],     Sacc[mt][2 * ks][0]));
                pa[mt][1] = ex2bf2(cvt2bf(Sacc[mt][2 * ks][3],     Sacc[mt][2 * ks][2]));
                pa[mt][2] = ex2bf2(cvt2bf(Sacc[mt][2 * ks + 1][1], Sacc[mt][2 * ks + 1][0]));
                pa[mt][3] = ex2bf2(cvt2bf(Sacc[mt][2 * ks + 1][3], Sacc[mt][2 * ks + 1][2]));
            }
            #pragma unroll
            for (int ng2 = 0; ng2 < 4; ng2++) {
                uint32_t v0, v1, v2, v3;
                ldsm4(vb + ng2 * 2304 + ks * 32, v0, v1, v2, v3);
                hmma(Oacc[0][2 * ng2],     pa[0][0], pa[0][1], pa[0][2], pa[0][3], v0, v1);
                hmma(Oacc[0][2 * ng2 + 1], pa[0][0], pa[0][1], pa[0][2], pa[0][3], v2, v3);
                hmma(Oacc[1][2 * ng2],     pa[1][0], pa[1][1], pa[1][2], pa[1][3], v0, v1);
                hmma(Oacc[1][2 * ng2 + 1], pa[1][0], pa[1][1], pa[1][2], pa[1][3], v2, v3);
            }
            hmma(Racc[0], pa[0][0], pa[0][1], pa[0][2], pa[0][3], ONESBF, ONESBF);
            hmma(Racc[1], pa[1][0], pa[1][1], pa[1][2], pa[1][3], ONESBF, ONESBF);
        }
    }

    // partial rowsums (all 8 output cols equal; lane tg==0 writes rows gp, gp+8)
    float* rsb = g_rs + (size_t)s * (CB * CH * CL) + (size_t)bh * CL + l0;
    if (tg == 0) {
        #pragma unroll
        for (int mt = 0; mt < 2; mt++) {
            rsb[w * 32 + mt * 16 + gp]     = Racc[mt][0];
            rsb[w * 32 + mt * 16 + gp + 8] = Racc[mt][2];
        }
    }

    __syncthreads();
    #pragma unroll
    for (int mt = 0; mt < 2; mt++) {
        int qb = w * 32 + mt * 16 + gp;
        #pragma unroll
        for (int n = 0; n < 8; n++) {
            int d = n * 8 + tg * 2;
            Osm[(d)     * 132 + qb]     = Oacc[mt][n][0];
            Osm[(d + 1) * 132 + qb]     = Oacc[mt][n][1];
            Osm[(d)     * 132 + qb + 8] = Oacc[mt][n][2];
            Osm[(d + 1) * 132 + qb + 8] = Oacc[mt][n][3];
        }
    }
    __syncthreads();

    float* ob = g_att + (size_t)s * (CB * CO * CL) + (size_t)bh * CC * CL + l0;
    for (int c = tid; c < 64 * 32; c += 128) {
        int d = c >> 5, q4 = (c & 31) << 2;
        *(float4*)&ob[(size_t)d * CL + q4] = *(const float4*)&Osm[d * 132 + q4];
    }
}

// ============================================================================
// Unify heads on tf32 HMMA; combines the two flash splits + normalizes + rna.
// Buf slot: O0 [64][68] @0, O1 @17408B, W [64][68] @34816B; 3 slots.
// ============================================================================
#define UB_STR  52224
#define U_SMEM  (3 * UB_STR)

__global__ void __launch_bounds__(256, 1) unify_kernel(
    const float* __restrict__ ub, float* __restrict__ y)
{
    extern __shared__ float usm[];
    uint32_t sbU = smem_u32(usm);

    int tid = threadIdx.x;
    int w = tid >> 5, ln = tid & 31, gp = ln >> 2, tg = ln & 3;
    int wm = w & 3, wn = w >> 2;
    int l0 = blockIdx.x * 64, b = blockIdx.y;

    auto issue = [&](int t) {
        uint32_t base = sbU + (t % 3) * UB_STR;
        const float* a0g = g_att + (size_t)(b * CO + t * 64) * CL + l0;
        const float* a1g = a0g + (size_t)CB * CO * CL;
        for (int i = tid; i < 1024; i += 256) {
            int o = i >> 4, j = i & 15;
            cpa16(base + o * 272 + j * 16, a0g + (size_t)o * CL + j * 4);
            cpa16(base + 17408 + o * 272 + j * 16, a1g + (size_t)o * CL + j * 4);
        }
        const float* wg = g_uwt + t * 64;
        for (int i = tid; i < 1024; i += 256) {
            int c = i >> 4, j = i & 15;
            cpa16(base + 34816 + c * 272 + j * 16, wg + (size_t)c * CO + j * 4);
        }
        CP_COMMIT();
    };

    issue(0);
    issue(1);

    float acc[4][4];
    #pragma unroll
    for (int ns = 0; ns < 4; ns++)
        #pragma unroll
        for (int r = 0; r < 4; r++) acc[ns][r] = 0.f;

    for (int t = 0; t < 8; t++) {
        if (t < 7) { CP_WAIT(1); } else { CP_WAIT(0); }
        __syncthreads();
        if (t + 2 < 8) issue(t + 2);

        float* O0 = usm + (t % 3) * (UB_STR / 4);   // [o][68 l]
        const float* O1 = O0 + 4352;
        const float* Aw = O0 + 8704;                // [c][68 o]

        // combine: att = (O0 + O1) / (rs0 + rs1), rna; in place into O0
        {
            int lcol = tid & 63, og = tid >> 6;
            const float* rs0 = g_rs + (size_t)(b * CH + t) * CL + l0;
            float inv = 1.0f / (rs0[lcol] + rs0[(size_t)CB * CH * CL + lcol]);
            #pragma unroll
            for (int k = 0; k < 16; k++) {
                int o = og * 16 + k;
                O0[o * 68 + lcol] = tf32rna((O0[o * 68 + lcol] + O1[o * 68 + lcol]) * inv);
            }
        }
        __syncthreads();

        #pragma unroll
        for (int ks = 0; ks < 8; ks++) {
            int k0 = ks * 8;
            int ra = (wm * 16 + gp) * 68 + k0;
            uint32_t a0 = *(const uint32_t*)&Aw[ra + tg];
            uint32_t a1 = *(const uint32_t*)&Aw[ra + 8 * 68 + tg];
            uint32_t a2 = *(const uint32_t*)&Aw[ra + tg + 4];
            uint32_t a3 = *(const uint32_t*)&Aw[ra + 8 * 68 + tg + 4];
            int rb0 = (k0 + tg) * 68 + wn * 32 + gp;
            int rb1 = (k0 + tg + 4) * 68 + wn * 32 + gp;
            #pragma unroll
            for (int ns = 0; ns < 4; ns++) {
                uint32_t b0 = *(const uint32_t*)&O0[rb0 + ns * 8];
                uint32_t b1 = *(const uint32_t*)&O0[rb1 + ns * 8];
                tmma(acc[ns], a0, a1, a2, a3, b0, b1);
            }
        }
    }

    __syncthreads();
    float* stg = usm;
    #pragma unroll
    for (int ns = 0; ns < 4; ns++) {
        int lcol = wn * 32 + ns * 8 + tg * 2;
        int c = wm * 16 + gp;
        *(float2*)&stg[(c)     * 68 + lcol] = make_float2(acc[ns][0], acc[ns][1]);
        *(float2*)&stg[(c + 8) * 68 + lcol] = make_float2(acc[ns][2], acc[ns][3]);
    }
    __syncthreads();

    for (int i = tid; i < 1024; i += 256) {
        int c = i >> 4, l4 = (i & 15) << 2;
        float bb = ub[c];
        float4 v = *(const float4*)&stg[c * 68 + l4];
        v.x += bb; v.y += bb; v.z += bb; v.w += bb;
        *(float4*)&y[(size_t)(b * CC + c) * CL + l0 + l4] = v;
    }
}

// ============================================================================
extern "C" void kernel_launch(void* const* d_in, const int* in_sizes, int n_in,
                              void* d_out, int out_size)
{
    (void)in_sizes; (void)n_in; (void)out_size;
    const float* x    = (const float*)d_in[0];
    const float* q_dw = (const float*)d_in[1];
    const float* q_db = (const float*)d_in[2];
    const float* q_pw = (const float*)d_in[3];
    const float* q_pb = (const float*)d_in[4];
    const float* k_dw = (const float*)d_in[5];
    const float* k_db = (const float*)d_in[6];
    const float* k_pw = (const float*)d_in[7];
    const float* k_pb = (const float*)d_in[8];
    const float* v_dw = (const float*)d_in[9];
    const float* v_db = (const float*)d_in[10];
    const float* v_pw = (const float*)d_in[11];
    const float* v_pb = (const float*)d_in[12];
    const float* u_w  = (const float*)d_in[13];
    const float* u_b  = (const float*)d_in[14];

    cudaFuncSetAttribute(qkv_kernel,
                         cudaFuncAttributeMaxDynamicSharedMemorySize, QKV_SMEM);
    cudaFuncSetAttribute(flash_kernel,
                         cudaFuncAttributeMaxDynamicSharedMemorySize, FL_SMEM);
    cudaFuncSetAttribute(unify_kernel,
                         cudaFuncAttributeMaxDynamicSharedMemorySize, U_SMEM);

    prep_kernel<<<128, 256>>>(q_pw, k_pw, v_pw, u_w);

    qkv_kernel<<<dim3(CL / 64, CB, 3), 512, QKV_SMEM>>>(
        x, q_dw, q_db, q_pb, k_dw, k_db, k_pb, v_dw, v_db, v_pb);

    flash_kernel<<<dim3(CL / 128, CH, CB * 2), 128, FL_SMEM>>>();

    unify_kernel<<<dim3(CL / 64, CB), 256, U_SMEM>>>(u_b, (float*)d_out);
}